// round 7
// baseline (speedup 1.0000x reference)
#include <cuda_runtime.h>
#include <cuda_fp16.h>
#include <float.h>
#include <stdint.h>

// VectorQuantize: z[16,256,32,32] f32, codebook[8192,256] f32
// fp16 mma.sync (f16 accum) GEMM -> per-(row,tile) fp32 min + 128-bit mask
// -> warp/row select + exact fp32 refine -> gather.

#define NPTS 16384
#define NC   256
#define NK   8192
#define ZQ_ELEMS 4194304
#define TM 128
#define TN 128
#define NTILE (NK / TN)      // 64
#define MARGIN 2.5e-2f

// ---------------- scratch ----------------
__device__ unsigned short g_ah[NPTS * NC];    // fp16(z)
__device__ unsigned short g_bh[NK * NC];      // fp16(-2cb)
__device__ float g_zf[NPTS * NC];             // fp32 z rows (refine)
__device__ float g_zn[NPTS];
__device__ float g_cn[NK];                    // |cb|^2
__device__ float g_tmin[(size_t)NPTS * NTILE];
__device__ unsigned g_tmask[(size_t)NPTS * NTILE * 4];
__device__ int g_idx[NPTS];

// smem layout for vq_gemm
#define SROWMIN 65536   // 128 x u32
#define SMASK   66048   // 128 x 4 x u32
#define SMEM_SZ 68608

// ---------------- PTX helpers ----------------
__device__ __forceinline__ uint32_t smem_u32(const void* p) {
    uint32_t a;
    asm("{ .reg .u64 t; cvta.to.shared.u64 t, %1; cvt.u32.u64 %0, t; }" : "=r"(a) : "l"(p));
    return a;
}
#define CP_ASYNC16(sm, gp) \
    asm volatile("cp.async.cg.shared.global [%0], [%1], 16;" :: "r"(sm), "l"(gp) : "memory")
#define CP_COMMIT() asm volatile("cp.async.commit_group;" ::: "memory")
#define CP_WAIT(n)  asm volatile("cp.async.wait_group %0;" :: "n"(n) : "memory")
#define LDSM_X4(r0, r1, r2, r3, ad) \
    asm volatile("ldmatrix.sync.aligned.m8n8.x4.shared.b16 {%0,%1,%2,%3}, [%4];" \
                 : "=r"(r0), "=r"(r1), "=r"(r2), "=r"(r3) : "r"(ad))
// fp16 accumulate HMMA: D(f16x2 x2) = A(f16) * B(f16) + D
#define MMA16816H(d, a0, a1, a2, a3, b0, b1) \
    asm volatile("mma.sync.aligned.m16n8k16.row.col.f16.f16.f16.f16 " \
                 "{%0,%1}, {%2,%3,%4,%5}, {%6,%7}, {%0,%1};" \
                 : "+r"((d)[0]), "+r"((d)[1]) \
                 : "r"(a0), "r"(a1), "r"(a2), "r"(a3), "r"(b0), "r"(b1))

__device__ __forceinline__ uint32_t fenc(float f) {
    uint32_t b = __float_as_uint(f);
    return (b & 0x80000000u) ? ~b : (b | 0x80000000u);
}
__device__ __forceinline__ float fdec(uint32_t u) {
    uint32_t b = (u & 0x80000000u) ? (u & 0x7FFFFFFFu) : ~u;
    return __uint_as_float(b);
}

// ---------------- fused prep: blocks [0,NK) = codebook rows, rest = z chunks ----------------
__global__ void prep_all(const float* __restrict__ cb, const float* __restrict__ z) {
    const int bid = blockIdx.x, t = threadIdx.x;
    if (bid < NK) {
        float v = cb[(size_t)bid * NC + t];
        __half h = __float2half_rn(-2.0f * v);
        g_bh[bid * NC + t] = *(unsigned short*)&h;
        __shared__ float red[256];
        red[t] = v * v;
        __syncthreads();
        for (int s = 128; s > 0; s >>= 1) { if (t < s) red[t] += red[t + s]; __syncthreads(); }
        if (t == 0) g_cn[bid] = red[0];
    } else {
        const int n = (bid - NK) * 256 + t;
        const int b = n >> 10, hw = n & 1023;
        const float* zp = z + (size_t)b * (NC * 1024) + hw;
        float acc = 0.f;
#pragma unroll 8
        for (int c = 0; c < NC; c++) {
            float v = zp[(size_t)c * 1024];
            g_zf[n * NC + c] = v;
            acc += v * v;
            __half h = __float2half_rn(v);
            g_ah[n * NC + c] = *(unsigned short*)&h;
        }
        g_zn[n] = acc;
    }
}

// ---------------- GEMM + summary epilogue ----------------
__device__ __forceinline__ void issue_loads(uint32_t sb, int buf,
                                            const unsigned short* A, const unsigned short* B,
                                            int kchunk, int t) {
    uint32_t ab = sb + buf * 32768;
    uint32_t bb = ab + 16384;
#pragma unroll
    for (int i = 0; i < 4; i++) {
        int e = i * 256 + t;
        int r = e >> 3, ck = e & 7;
        int sw = (ck * 16) ^ ((r & 7) * 16);
        CP_ASYNC16(ab + r * 128 + sw, A + (size_t)r * NC + kchunk * 64 + ck * 8);
        CP_ASYNC16(bb + r * 128 + sw, B + (size_t)r * NC + kchunk * 64 + ck * 8);
    }
}

__global__ void __launch_bounds__(256) vq_gemm() {
    extern __shared__ char smem[];
    const uint32_t sb = smem_u32(smem);
    const int t = threadIdx.x;
    const int lane = t & 31, wid = t >> 5;
    const int warp_m = wid >> 1, warp_n = wid & 1;   // 4x2 warps -> 32x64 per warp
    const int tile = blockIdx.x;
    const int col0 = tile * TN;
    const int row0 = blockIdx.y * TM;
    const unsigned short* A = g_ah + (size_t)row0 * NC;
    const unsigned short* B = g_bh + (size_t)col0 * NC;

    uint32_t* rowmin = (uint32_t*)(smem + SROWMIN);
    uint32_t* maskw  = (uint32_t*)(smem + SMASK);
    if (t < TM) rowmin[t] = fenc(FLT_MAX);
    maskw[t] = 0; maskw[t + 256] = 0;

    uint32_t d[2][8][2];   // fp16x2 accumulators
#pragma unroll
    for (int i = 0; i < 2; i++)
#pragma unroll
        for (int j = 0; j < 8; j++) { d[i][j][0] = 0u; d[i][j][1] = 0u; }

    issue_loads(sb, 0, A, B, 0, t);
    CP_COMMIT();

    for (int kc = 0; kc < 4; kc++) {
        if (kc < 3) {
            issue_loads(sb, (kc + 1) & 1, A, B, kc + 1, t);
            CP_COMMIT();
            CP_WAIT(1);
        } else {
            CP_WAIT(0);
        }
        __syncthreads();

        const uint32_t Ab = sb + (kc & 1) * 32768;
        const uint32_t Bb = Ab + 16384;
#pragma unroll
        for (int ks = 0; ks < 4; ks++) {
            const int c2 = ks * 32 + (lane >> 4) * 16;
            uint32_t a[2][4];
#pragma unroll
            for (int mt = 0; mt < 2; mt++) {
                int row = warp_m * 32 + mt * 16 + (lane & 15);
                uint32_t ad = Ab + row * 128 + (c2 ^ ((row & 7) * 16));
                LDSM_X4(a[mt][0], a[mt][1], a[mt][2], a[mt][3], ad);
            }
            uint32_t bq[4][4];
#pragma unroll
            for (int np = 0; np < 4; np++) {
                int brow = warp_n * 64 + np * 16 + (lane & 15);
                uint32_t bd = Bb + brow * 128 + (c2 ^ ((brow & 7) * 16));
                LDSM_X4(bq[np][0], bq[np][1], bq[np][2], bq[np][3], bd);
            }
#pragma unroll
            for (int mt = 0; mt < 2; mt++)
#pragma unroll
                for (int np = 0; np < 4; np++) {
                    MMA16816H(d[mt][np * 2],     a[mt][0], a[mt][1], a[mt][2], a[mt][3],
                              bq[np][0], bq[np][2]);
                    MMA16816H(d[mt][np * 2 + 1], a[mt][0], a[mt][1], a[mt][2], a[mt][3],
                              bq[np][1], bq[np][3]);
                }
        }
        __syncthreads();
    }

    // ---- summary epilogue (unpack fp16 accum -> fp32 scores) ----
    const int g = lane >> 2, tig = lane & 3;
    float sc[2][8][4];
#pragma unroll
    for (int nt = 0; nt < 8; nt++) {
        const int scol = col0 + warp_n * 64 + nt * 8 + 2 * tig;
        const float cn0 = __ldg(&g_cn[scol]);
        const float cn1 = __ldg(&g_cn[scol + 1]);
#pragma unroll
        for (int mt = 0; mt < 2; mt++) {
            float2 p01 = __half22float2(*(half2*)&d[mt][nt][0]);
            float2 p23 = __half22float2(*(half2*)&d[mt][nt][1]);
            sc[mt][nt][0] = p01.x + cn0;
            sc[mt][nt][1] = p01.y + cn1;
            sc[mt][nt][2] = p23.x + cn0;
            sc[mt][nt][3] = p23.y + cn1;
        }
    }
    // pass 1: per-row tile min
#pragma unroll
    for (int mt = 0; mt < 2; mt++) {
        const int r0 = warp_m * 32 + mt * 16 + g;
        float mn0 = FLT_MAX, mn1 = FLT_MAX;
#pragma unroll
        for (int nt = 0; nt < 8; nt++) {
            mn0 = fminf(mn0, fminf(sc[mt][nt][0], sc[mt][nt][1]));
            mn1 = fminf(mn1, fminf(sc[mt][nt][2], sc[mt][nt][3]));
        }
        atomicMin(&rowmin[r0],     fenc(mn0));
        atomicMin(&rowmin[r0 + 8], fenc(mn1));
    }
    __syncthreads();
    // pass 2: candidate mask
#pragma unroll
    for (int mt = 0; mt < 2; mt++) {
        const int r0 = warp_m * 32 + mt * 16 + g;
        const float th0 = fdec(rowmin[r0]) + MARGIN;
        const float th1 = fdec(rowmin[r0 + 8]) + MARGIN;
#pragma unroll
        for (int nt = 0; nt < 8; nt++) {
            const int c = warp_n * 64 + nt * 8 + 2 * tig;
            if (sc[mt][nt][0] <= th0) atomicOr(&maskw[r0 * 4 + (c >> 5)], 1u << (c & 31));
            if (sc[mt][nt][1] <= th0) atomicOr(&maskw[r0 * 4 + ((c + 1) >> 5)], 1u << ((c + 1) & 31));
            if (sc[mt][nt][2] <= th1) atomicOr(&maskw[(r0 + 8) * 4 + (c >> 5)], 1u << (c & 31));
            if (sc[mt][nt][3] <= th1) atomicOr(&maskw[(r0 + 8) * 4 + ((c + 1) >> 5)], 1u << ((c + 1) & 31));
        }
    }
    __syncthreads();
    if (t < TM) g_tmin[(size_t)(row0 + t) * NTILE + tile] = fdec(rowmin[t]);
#pragma unroll
    for (int i = 0; i < 2; i++) {
        int e = i * 256 + t;
        int r = e >> 2, w = e & 3;
        g_tmask[((size_t)(row0 + r) * NTILE + tile) * 4 + w] = maskw[r * 4 + w];
    }
}

// ---------------- select + exact fp32 refine: one warp per row ----------------
__global__ void __launch_bounds__(256) vq_select(const float* __restrict__ cb) {
    const int lane = threadIdx.x & 31;
    const int row = blockIdx.x * 8 + (threadIdx.x >> 5);

    const float* tm = g_tmin + (size_t)row * NTILE;
    const float v0 = tm[lane], v1 = tm[lane + 32];
    float m = fminf(v0, v1);
#pragma unroll
    for (int o = 16; o > 0; o >>= 1) m = fminf(m, __shfl_xor_sync(0xffffffffu, m, o));
    const float thr = m + MARGIN;

    float z8[8];
#pragma unroll
    for (int i = 0; i < 8; i++) z8[i] = g_zf[(size_t)row * NC + lane * 8 + i];
    const float zn = g_zn[row];

    float bv = FLT_MAX;
    int bi = 0x7fffffff;

    unsigned bal[2];
    bal[0] = __ballot_sync(0xffffffffu, v0 <= thr);
    bal[1] = __ballot_sync(0xffffffffu, v1 <= thr);
#pragma unroll
    for (int p = 0; p < 2; p++) {
        unsigned bits = bal[p];
        while (bits) {
            const int tile = p * 32 + (__ffs(bits) - 1);
            bits &= bits - 1;
            const uint4 mk = *(const uint4*)(g_tmask + ((size_t)row * NTILE + tile) * 4);
            unsigned w[4] = { mk.x, mk.y, mk.z, mk.w };
#pragma unroll
            for (int wi = 0; wi < 4; wi++) {
                unsigned ww = w[wi];
                while (ww) {
                    const int b = __ffs(ww) - 1;
                    ww &= ww - 1;
                    const int k = tile * TN + wi * 32 + b;
                    const float* cbr = cb + (size_t)k * NC + lane * 8;
                    float s = 0.f;
#pragma unroll
                    for (int i = 0; i < 8; i++) s = fmaf(z8[i], -2.0f * cbr[i], s);
#pragma unroll
                    for (int o = 16; o > 0; o >>= 1) s += __shfl_xor_sync(0xffffffffu, s, o);
                    const float dd = (s + zn) + g_cn[k];
                    if (dd < bv || (dd == bv && k < bi)) { bv = dd; bi = k; }
                }
            }
        }
    }
    if (lane == 0) g_idx[row] = bi;
}

// ---------------- outputs: gather + idx tail in one kernel ----------------
__global__ void vq_out(const float* __restrict__ cb, float* __restrict__ out, int emit_idx) {
    int o = blockIdx.x * blockDim.x + threadIdx.x;
    if (o < ZQ_ELEMS) {
        int w = o & 31;
        int h = (o >> 5) & 31;
        int c = (o >> 10) & 255;
        int b = o >> 18;
        int n = (b << 10) + (h << 5) + w;
        out[o] = cb[(size_t)g_idx[n] * NC + c];
    } else if (emit_idx) {
        int n = o - ZQ_ELEMS;
        out[ZQ_ELEMS + n] = (float)g_idx[n];
    }
}

extern "C" void kernel_launch(void* const* d_in, const int* in_sizes, int n_in,
                              void* d_out, int out_size) {
    const float* z  = (const float*)d_in[0];
    const float* cb = (const float*)d_in[1];
    if (n_in >= 2 && in_sizes[0] == NK * NC && in_sizes[1] == NPTS * NC) {
        const float* tmp = z; z = cb; cb = tmp;
    }
    float* out = (float*)d_out;

    cudaFuncSetAttribute(vq_gemm, cudaFuncAttributeMaxDynamicSharedMemorySize, SMEM_SZ);

    prep_all<<<NK + NPTS / 256, 256>>>(cb, z);
    vq_gemm<<<dim3(NK / TN, NPTS / TM), 256, SMEM_SZ>>>();
    vq_select<<<NPTS / 8, 256>>>(cb);
    const int emit = (out_size >= ZQ_ELEMS + NPTS);
    vq_out<<<(ZQ_ELEMS + (emit ? NPTS : 0)) / 256, 256>>>(cb, out, emit);
}